// round 7
// baseline (speedup 1.0000x reference)
#include <cuda_runtime.h>
#include <cuda_fp16.h>
#include <cstdint>

typedef unsigned long long u64;
typedef unsigned int u32;

#define Bc 64
#define Tc 512
#define T2c 514
#define Ec 256
#define Hc 256
#define Vc 5000

// scratch (allocation-free rule: __device__ globals)
__device__ float g_pre[Bc * Tc * Hc];
__device__ __half g_ahi[Bc * Tc * Hc];
__device__ __half g_alo[Bc * Tc * Hc];
__device__ __half g_whi[Vc * Hc];

// ---------------- helpers ----------------
__device__ __forceinline__ u32 smem_u32(const void* p) {
    u32 a; asm("{ .reg .u64 t; cvta.to.shared.u64 t, %1; cvt.u32.u64 %0, t; }" : "=r"(a) : "l"(p));
    return a;
}
__device__ __forceinline__ u64 pk2(float x, float y) {
    u64 r; asm("mov.b64 %0,{%1,%2};" : "=l"(r) : "f"(x), "f"(y)); return r;
}
__device__ __forceinline__ u64 fma2(u64 a, u64 b, u64 c) {
    u64 d; asm("fma.rn.f32x2 %0,%1,%2,%3;" : "=l"(d) : "l"(a), "l"(b), "l"(c)); return d;
}
__device__ __forceinline__ float2 up2(u64 p) {
    float2 r; asm("mov.b64 {%0,%1},%2;" : "=f"(r.x), "=f"(r.y) : "l"(p)); return r;
}
__device__ __forceinline__ void ldsm_x4(u32* r, u32 addr) {
    asm volatile("ldmatrix.sync.aligned.m8n8.x4.shared.b16 {%0,%1,%2,%3}, [%4];"
                 : "=r"(r[0]), "=r"(r[1]), "=r"(r[2]), "=r"(r[3]) : "r"(addr));
}
__device__ __forceinline__ void mma_f16(float* d, const u32* a, const u32* b) {
    asm volatile(
        "mma.sync.aligned.m16n8k16.row.col.f32.f16.f16.f32 "
        "{%0,%1,%2,%3},{%4,%5,%6,%7},{%8,%9},{%0,%1,%2,%3};"
        : "+f"(d[0]), "+f"(d[1]), "+f"(d[2]), "+f"(d[3])
        : "r"(a[0]), "r"(a[1]), "r"(a[2]), "r"(a[3]), "r"(b[0]), "r"(b[1]));
}
__device__ __forceinline__ void cpa16(u32 dst, const void* src, u32 sz) {
    asm volatile("cp.async.cg.shared.global [%0], [%1], 16, %2;"
                 :: "r"(dst), "l"(src), "r"(sz) : "memory");
}
__device__ __forceinline__ void cp_commit() {
    asm volatile("cp.async.commit_group;" ::: "memory");
}
__device__ __forceinline__ float tanh_acc(float x) {
    float ax = fabsf(x);
    float e;
    asm("ex2.approx.f32 %0, %1;" : "=f"(e) : "f"(-2.885390082f * ax)); // exp(-2|x|)
    float denom;
    asm("rcp.approx.f32 %0, %1;" : "=f"(denom) : "f"(1.0f + e));
    float t = (1.0f - e) * denom;
    return copysignf(t, x);
}
__device__ __forceinline__ void mbar_init(u32 a, u32 cnt) {
    asm volatile("mbarrier.init.shared.b64 [%0], %1;" :: "r"(a), "r"(cnt) : "memory");
}
__device__ __forceinline__ void mbar_arrive_expect(u32 a, u32 tx) {
    asm volatile("mbarrier.arrive.expect_tx.shared.b64 _, [%0], %1;"
                 :: "r"(a), "r"(tx) : "memory");
}
__device__ __forceinline__ void mbar_wait(u32 a, u32 parity) {
    asm volatile(
        "{\n\t.reg .pred P1;\n\t"
        "WL%=:\n\t"
        "mbarrier.try_wait.parity.acquire.cta.shared::cta.b64 P1, [%0], %1, 0x989680;\n\t"
        "@P1 bra WD%=;\n\t"
        "bra WL%=;\n\t"
        "WD%=:\n\t}"
        :: "r"(a), "r"(parity) : "memory");
}
__device__ __forceinline__ u32 mapa_u32(u32 local, u32 rank) {
    u32 o; asm("mapa.shared::cluster.u32 %0, %1, %2;" : "=r"(o) : "r"(local), "r"(rank));
    return o;
}
__device__ __forceinline__ void st_async_f32(u32 raddr, float v, u32 rmbar) {
    asm volatile("st.async.weak.shared::cluster.mbarrier::complete_tx::bytes.b32 [%0], %1, [%2];"
                 :: "r"(raddr), "f"(v), "r"(rmbar) : "memory");
}

// ---------------- embedding gather -> fp16 hi/lo ----------------
__global__ void embed_kernel(const int* __restrict__ x, const float* __restrict__ tab,
                             __half* __restrict__ hi, __half* __restrict__ lo) {
    int bt = blockIdx.x;
    int b = bt >> 9, t = bt & 511;
    int tok = x[b * T2c + t];
    float4 v = reinterpret_cast<const float4*>(tab + (size_t)tok * Ec)[threadIdx.x];
    __half h0 = __float2half_rn(v.x), h1 = __float2half_rn(v.y);
    __half h2 = __float2half_rn(v.z), h3 = __float2half_rn(v.w);
    __half l0 = __float2half_rn(v.x - __half2float(h0));
    __half l1 = __float2half_rn(v.y - __half2float(h1));
    __half l2 = __float2half_rn(v.z - __half2float(h2));
    __half l3 = __float2half_rn(v.w - __half2float(h3));
    size_t o = (size_t)bt * Ec + threadIdx.x * 4;
    *reinterpret_cast<ushort4*>(hi + o) = make_ushort4(
        __half_as_ushort(h0), __half_as_ushort(h1), __half_as_ushort(h2), __half_as_ushort(h3));
    *reinterpret_cast<ushort4*>(lo + o) = make_ushort4(
        __half_as_ushort(l0), __half_as_ushort(l1), __half_as_ushort(l2), __half_as_ushort(l3));
}

// ---------------- fp32 weights -> plain fp16 ----------------
__global__ void convw_kernel(const float* __restrict__ src, __half* __restrict__ dst) {
    size_t i = ((size_t)blockIdx.x * 256 + threadIdx.x) * 4;
    float4 v = *reinterpret_cast<const float4*>(src + i);
    *reinterpret_cast<ushort4*>(dst + i) = make_ushort4(
        __half_as_ushort(__float2half_rn(v.x)), __half_as_ushort(__float2half_rn(v.y)),
        __half_as_ushort(__float2half_rn(v.z)), __half_as_ushort(__float2half_rn(v.w)));
}

// ---------------- HMMA fp16 2-term GEMM (unchanged from R5) ----------------
#define TILE_B 10240
#define STAGE_B (3 * TILE_B)
#define GEMM_SMEM (3 * STAGE_B)

__global__ void __launch_bounds__(256, 2) mma_gemm(
    const __half* __restrict__ Ahi, const __half* __restrict__ Alo,
    const __half* __restrict__ Bh,
    const float* __restrict__ bias, float* __restrict__ C, int Nact)
{
    extern __shared__ __align__(16) char smem[];
    const u32 sb = smem_u32(smem);
    const int tid = threadIdx.x;
    const int wid = tid >> 5, lane = tid & 31;
    const int m0 = blockIdx.y * 128, n0 = blockIdx.x * 128;
    const int wm = (wid >> 2) * 64, wn = (wid & 3) * 32;

    const int row0 = tid >> 2, seg0 = tid & 3;
    const int row1 = (tid + 256) >> 2, seg1 = (tid + 256) & 3;

    float acc[4][4][4];
#pragma unroll
    for (int i = 0; i < 4; i++)
#pragma unroll
        for (int j = 0; j < 4; j++)
#pragma unroll
            for (int q = 0; q < 4; q++) acc[i][j][q] = 0.f;

    auto load_chunk = [&](int k0, int stage) {
        const u32 base = sb + stage * STAGE_B;
#pragma unroll
        for (int h = 0; h < 2; h++) {
            const int row = h ? row1 : row0;
            const int seg = h ? seg1 : seg0;
            const u32 dst = base + row * 80 + seg * 16;
            const size_t aoff = (size_t)(m0 + row) * 256 + k0 + seg * 8;
            cpa16(dst, Ahi + aoff, 16);
            cpa16(dst + TILE_B, Alo + aoff, 16);
            const int br = n0 + row;
            const u32 sz = (br < Nact) ? 16u : 0u;
            const int brc = (br < Nact) ? br : (Nact - 1);
            cpa16(dst + 2 * TILE_B, Bh + (size_t)brc * 256 + k0 + seg * 8, sz);
        }
        cp_commit();
    };

    const u32 arow = (wm + (lane & 15)) * 80 + (lane >> 4) * 16;
    const u32 brow = (wn + (lane & 7) + ((lane >> 4) & 1) * 8) * 80 + ((lane >> 3) & 1) * 16;

    load_chunk(0, 0);
    load_chunk(32, 1);

#pragma unroll 1
    for (int ic = 0; ic < 8; ic++) {
        if (ic < 7) asm volatile("cp.async.wait_group 1;" ::: "memory");
        else        asm volatile("cp.async.wait_group 0;" ::: "memory");
        __syncthreads();
        if (ic < 6) load_chunk((ic + 2) * 32, (ic + 2) % 3);

        const u32 base = sb + (ic % 3) * STAGE_B;
        const u32 aHi = base, aLo = base + TILE_B, bHm = base + 2 * TILE_B;
#pragma unroll
        for (int kk = 0; kk < 2; kk++) {
            u32 af[4][4], bf[2][4];
#pragma unroll
            for (int jb = 0; jb < 2; jb++)
                ldsm_x4(bf[jb], bHm + brow + jb * 16 * 80 + kk * 32);
#pragma unroll
            for (int im = 0; im < 4; im++)
                ldsm_x4(af[im], aHi + arow + im * 16 * 80 + kk * 32);
#pragma unroll
            for (int im = 0; im < 4; im++)
#pragma unroll
                for (int jn = 0; jn < 4; jn++)
                    mma_f16(acc[im][jn], af[im], &bf[jn >> 1][(jn & 1) * 2]);
#pragma unroll
            for (int im = 0; im < 4; im++)
                ldsm_x4(af[im], aLo + arow + im * 16 * 80 + kk * 32);
#pragma unroll
            for (int im = 0; im < 4; im++)
#pragma unroll
                for (int jn = 0; jn < 4; jn++)
                    mma_f16(acc[im][jn], af[im], &bf[jn >> 1][(jn & 1) * 2]);
        }
    }

    const int rbase = m0 + wm + (lane >> 2);
    const int cbase = n0 + wn + (lane & 3) * 2;
#pragma unroll
    for (int im = 0; im < 4; im++) {
#pragma unroll
        for (int jn = 0; jn < 4; jn++) {
            int n = cbase + jn * 8;
            if (n < Nact) {
                float bx = bias[n], by = bias[n + 1];
                int r0 = rbase + im * 16;
                *reinterpret_cast<float2*>(C + (size_t)r0 * Nact + n) =
                    make_float2(acc[im][jn][0] + bx, acc[im][jn][1] + by);
                *reinterpret_cast<float2*>(C + (size_t)(r0 + 8) * Nact + n) =
                    make_float2(acc[im][jn][2] + bx, acc[im][jn][3] + by);
            }
        }
    }
}

// ---------------- recurrence v5: cluster-of-2, all weights in registers ----------------
// 2 CTAs per batch; CTA rank q owns output rows [q*128, q*128+128).
// 512 threads = 128 rows x 4 k-quarters; 64 weights/thread in 32 u64 regs (no smem, no spill).
// Quarter partials reduced by shfl.bfly. Row owner (quarter 0) computes tanh, writes h to
// local smem + peer smem (st.async + mbarrier complete_tx). Double-buffered h, 2 mbarriers.
__global__ void __launch_bounds__(512, 1) __cluster_dims__(2, 1, 1)
rnn_scan(const float* __restrict__ pre, const float* __restrict__ Whh,
         const float* __restrict__ bhh, __half* __restrict__ outhi, __half* __restrict__ outlo,
         float* __restrict__ hlast)
{
    __shared__ __align__(16) float hbuf[2][256];
    __shared__ __align__(8) u64 mbar[2];
    const int b = blockIdx.x >> 1;
    u32 rank; asm("mov.u32 %0, %%cluster_ctarank;" : "=r"(rank));
    const int tid = threadIdx.x;
    const int rowl = tid >> 2, quarter = tid & 3;
    const int r = (int)rank * 128 + rowl;

    // 64 weights in registers
    u64 wreg[32];
    const float* wrow = Whh + (size_t)r * 256 + quarter * 64;
#pragma unroll
    for (int j = 0; j < 16; j++) {
        ulonglong2 v = *reinterpret_cast<const ulonglong2*>(wrow + j * 4);
        wreg[2 * j] = v.x; wreg[2 * j + 1] = v.y;
    }

    const u32 mb[2] = { smem_u32(&mbar[0]), smem_u32(&mbar[1]) };
    const u32 hb[2] = { smem_u32(&hbuf[0][0]), smem_u32(&hbuf[1][0]) };
    if (tid < 256) hbuf[0][tid] = 0.f;
    if (tid == 0) { mbar_init(mb[0], 1); mbar_init(mb[1], 1); }
    __syncthreads();
    asm volatile("barrier.cluster.arrive.aligned;" ::: "memory");
    asm volatile("barrier.cluster.wait.aligned;" ::: "memory");

    const u32 peer = rank ^ 1u;
    const u32 pmb[2] = { mapa_u32(mb[0], peer), mapa_u32(mb[1], peer) };
    const u32 phb[2] = { mapa_u32(hb[0], peer), mapa_u32(hb[1], peer) };

    const float* preb = pre + (size_t)b * Tc * Hc;
    __half* ohi = outhi + (size_t)b * Tc * Hc;
    __half* olo = outlo + (size_t)b * Tc * Hc;

    float bias = 0.f, pc = 0.f;
    if (quarter == 0) { bias = bhh[r]; pc = preb[r]; }

    float hn = 0.f;
#pragma unroll 1
    for (int t = 0; t < Tc; t++) {
        if (t > 0) mbar_wait(mb[t & 1], ((t - 1) >> 1) & 1);   // peer half of h_t arrived
        if (tid == 0) mbar_arrive_expect(mb[(t + 1) & 1], 512);

        const ulonglong2* hc =
            reinterpret_cast<const ulonglong2*>(&hbuf[t & 1][quarter * 64]);
        u64 a0 = 0ull, a1 = 0ull;
#pragma unroll
        for (int j = 0; j < 16; j++) {
            ulonglong2 h = hc[j];
            a0 = fma2(wreg[2 * j], h.x, a0);
            a1 = fma2(wreg[2 * j + 1], h.y, a1);
        }
        float2 p0 = up2(a0), p1 = up2(a1);
        float partial = (p0.x + p0.y) + (p1.x + p1.y);
        partial += __shfl_xor_sync(0xFFFFFFFFu, partial, 1);
        partial += __shfl_xor_sync(0xFFFFFFFFu, partial, 2);

        if (quarter == 0) {
            int tn = (t + 1 < Tc) ? t + 1 : t;
            float pn = preb[tn * Hc + r];                      // prefetch next step
            hn = tanh_acc(pc + bias + partial);
            __half hh = __float2half_rn(hn);
            __half hl = __float2half_rn(hn - __half2float(hh));
            ohi[t * Hc + r] = hh;
            olo[t * Hc + r] = hl;
            hbuf[(t + 1) & 1][r] = hn;                         // local copy
            st_async_f32(phb[(t + 1) & 1] + r * 4, hn, pmb[(t + 1) & 1]);  // peer copy
            pc = pn;
        }
        __syncthreads();
    }
    if (quarter == 0) hlast[b * Hc + r] = hn;
    asm volatile("barrier.cluster.arrive.aligned;" ::: "memory");
    asm volatile("barrier.cluster.wait.aligned;" ::: "memory");
}

__global__ void tail_kernel(const int* __restrict__ x, float* __restrict__ outSeq) {
    int i = threadIdx.x;
    outSeq[i] = (float)x[i * T2c + (T2c - 1)];
}

extern "C" void kernel_launch(void* const* d_in, const int* in_sizes, int n_in,
                              void* d_out, int out_size) {
    const int*   x    = (const int*)d_in[0];
    const float* tab  = (const float*)d_in[1];
    const float* Wih  = (const float*)d_in[2];
    const float* Whh  = (const float*)d_in[3];
    const float* bih  = (const float*)d_in[4];
    const float* bhh  = (const float*)d_in[5];
    const float* Wout = (const float*)d_in[6];
    const float* bout = (const float*)d_in[7];
    float* out = (float*)d_out;

    float* pre;
    __half *ahi, *alo, *whi;
    cudaGetSymbolAddress((void**)&pre, g_pre);
    cudaGetSymbolAddress((void**)&ahi, g_ahi);
    cudaGetSymbolAddress((void**)&alo, g_alo);
    cudaGetSymbolAddress((void**)&whi, g_whi);

    cudaFuncSetAttribute(mma_gemm, cudaFuncAttributeMaxDynamicSharedMemorySize, GEMM_SMEM);

    const size_t LOGITS = (size_t)Bc * Tc * Vc;
    float* lstate = out + LOGITS;
    float* seq = out + LOGITS + 2 * Bc * Hc;

    embed_kernel<<<Bc * Tc, 64>>>(x, tab, ahi, alo);

    dim3 blk(256);
    // layer 0
    convw_kernel<<<(Hc * Ec) / 1024, 256>>>(Wih, whi);
    mma_gemm<<<dim3(2, 256), blk, GEMM_SMEM>>>(ahi, alo, whi, bih, pre, Hc);
    rnn_scan<<<2 * Bc, 512>>>(pre, Whh, bhh, ahi, alo, lstate);
    // layer 1
    convw_kernel<<<(Hc * Ec) / 1024, 256>>>(Wih + Hc * Ec, whi);
    mma_gemm<<<dim3(2, 256), blk, GEMM_SMEM>>>(ahi, alo, whi, bih + Hc, pre, Hc);
    rnn_scan<<<2 * Bc, 512>>>(pre, Whh + Hc * Hc, bhh + Hc, ahi, alo, lstate + Bc * Hc);
    // output projection
    convw_kernel<<<(Vc * Hc) / 1024, 256>>>(Wout, whi);
    mma_gemm<<<dim3((Vc + 127) / 128, 256), blk, GEMM_SMEM>>>(ahi, alo, whi, bout, out, Vc);

    tail_kernel<<<1, Bc>>>(x, seq);
}

// round 8
// speedup vs baseline: 1.6215x; 1.6215x over previous
#include <cuda_runtime.h>
#include <cuda_fp16.h>
#include <cstdint>

typedef unsigned long long u64;
typedef unsigned int u32;

#define Bc 64
#define Tc 512
#define T2c 514
#define Ec 256
#define Hc 256
#define Vc 5000

// scratch (allocation-free rule: __device__ globals)
__device__ float g_pre[Bc * Tc * Hc];
__device__ __half g_ahi[Bc * Tc * Hc];
__device__ __half g_alo[Bc * Tc * Hc];
__device__ __half g_whi[Vc * Hc];

// ---------------- helpers ----------------
__device__ __forceinline__ u32 smem_u32(const void* p) {
    u32 a; asm("{ .reg .u64 t; cvta.to.shared.u64 t, %1; cvt.u32.u64 %0, t; }" : "=r"(a) : "l"(p));
    return a;
}
__device__ __forceinline__ u64 pk2(float x, float y) {
    u64 r; asm("mov.b64 %0,{%1,%2};" : "=l"(r) : "f"(x), "f"(y)); return r;
}
__device__ __forceinline__ u64 fma2(u64 a, u64 b, u64 c) {
    u64 d; asm("fma.rn.f32x2 %0,%1,%2,%3;" : "=l"(d) : "l"(a), "l"(b), "l"(c)); return d;
}
__device__ __forceinline__ float2 up2(u64 p) {
    float2 r; asm("mov.b64 {%0,%1},%2;" : "=f"(r.x), "=f"(r.y) : "l"(p)); return r;
}
__device__ __forceinline__ void ldsm_x4(u32* r, u32 addr) {
    asm volatile("ldmatrix.sync.aligned.m8n8.x4.shared.b16 {%0,%1,%2,%3}, [%4];"
                 : "=r"(r[0]), "=r"(r[1]), "=r"(r[2]), "=r"(r[3]) : "r"(addr));
}
__device__ __forceinline__ void mma_f16(float* d, const u32* a, const u32* b) {
    asm volatile(
        "mma.sync.aligned.m16n8k16.row.col.f32.f16.f16.f32 "
        "{%0,%1,%2,%3},{%4,%5,%6,%7},{%8,%9},{%0,%1,%2,%3};"
        : "+f"(d[0]), "+f"(d[1]), "+f"(d[2]), "+f"(d[3])
        : "r"(a[0]), "r"(a[1]), "r"(a[2]), "r"(a[3]), "r"(b[0]), "r"(b[1]));
}
__device__ __forceinline__ void cpa16(u32 dst, const void* src, u32 sz) {
    asm volatile("cp.async.cg.shared.global [%0], [%1], 16, %2;"
                 :: "r"(dst), "l"(src), "r"(sz) : "memory");
}
__device__ __forceinline__ void cp_commit() {
    asm volatile("cp.async.commit_group;" ::: "memory");
}
__device__ __forceinline__ float tanh_acc(float x) {
    float ax = fabsf(x);
    float e;
    asm("ex2.approx.f32 %0, %1;" : "=f"(e) : "f"(-2.885390082f * ax)); // exp(-2|x|)
    float denom;
    asm("rcp.approx.f32 %0, %1;" : "=f"(denom) : "f"(1.0f + e));
    float t = (1.0f - e) * denom;
    return copysignf(t, x);
}

// ---------------- embedding gather -> fp16 hi/lo ----------------
__global__ void embed_kernel(const int* __restrict__ x, const float* __restrict__ tab,
                             __half* __restrict__ hi, __half* __restrict__ lo) {
    int bt = blockIdx.x;
    int b = bt >> 9, t = bt & 511;
    int tok = x[b * T2c + t];
    float4 v = reinterpret_cast<const float4*>(tab + (size_t)tok * Ec)[threadIdx.x];
    __half h0 = __float2half_rn(v.x), h1 = __float2half_rn(v.y);
    __half h2 = __float2half_rn(v.z), h3 = __float2half_rn(v.w);
    __half l0 = __float2half_rn(v.x - __half2float(h0));
    __half l1 = __float2half_rn(v.y - __half2float(h1));
    __half l2 = __float2half_rn(v.z - __half2float(h2));
    __half l3 = __float2half_rn(v.w - __half2float(h3));
    size_t o = (size_t)bt * Ec + threadIdx.x * 4;
    *reinterpret_cast<ushort4*>(hi + o) = make_ushort4(
        __half_as_ushort(h0), __half_as_ushort(h1), __half_as_ushort(h2), __half_as_ushort(h3));
    *reinterpret_cast<ushort4*>(lo + o) = make_ushort4(
        __half_as_ushort(l0), __half_as_ushort(l1), __half_as_ushort(l2), __half_as_ushort(l3));
}

// ---------------- fp32 weights -> plain fp16 ----------------
__global__ void convw_kernel(const float* __restrict__ src, __half* __restrict__ dst) {
    size_t i = ((size_t)blockIdx.x * 256 + threadIdx.x) * 4;
    float4 v = *reinterpret_cast<const float4*>(src + i);
    *reinterpret_cast<ushort4*>(dst + i) = make_ushort4(
        __half_as_ushort(__float2half_rn(v.x)), __half_as_ushort(__float2half_rn(v.y)),
        __half_as_ushort(__float2half_rn(v.z)), __half_as_ushort(__float2half_rn(v.w)));
}

// ---------------- HMMA fp16 2-term GEMM (unchanged from R5) ----------------
#define TILE_B 10240
#define STAGE_B (3 * TILE_B)
#define GEMM_SMEM (3 * STAGE_B)

__global__ void __launch_bounds__(256, 2) mma_gemm(
    const __half* __restrict__ Ahi, const __half* __restrict__ Alo,
    const __half* __restrict__ Bh,
    const float* __restrict__ bias, float* __restrict__ C, int Nact)
{
    extern __shared__ __align__(16) char smem[];
    const u32 sb = smem_u32(smem);
    const int tid = threadIdx.x;
    const int wid = tid >> 5, lane = tid & 31;
    const int m0 = blockIdx.y * 128, n0 = blockIdx.x * 128;
    const int wm = (wid >> 2) * 64, wn = (wid & 3) * 32;

    const int row0 = tid >> 2, seg0 = tid & 3;
    const int row1 = (tid + 256) >> 2, seg1 = (tid + 256) & 3;

    float acc[4][4][4];
#pragma unroll
    for (int i = 0; i < 4; i++)
#pragma unroll
        for (int j = 0; j < 4; j++)
#pragma unroll
            for (int q = 0; q < 4; q++) acc[i][j][q] = 0.f;

    auto load_chunk = [&](int k0, int stage) {
        const u32 base = sb + stage * STAGE_B;
#pragma unroll
        for (int h = 0; h < 2; h++) {
            const int row = h ? row1 : row0;
            const int seg = h ? seg1 : seg0;
            const u32 dst = base + row * 80 + seg * 16;
            const size_t aoff = (size_t)(m0 + row) * 256 + k0 + seg * 8;
            cpa16(dst, Ahi + aoff, 16);
            cpa16(dst + TILE_B, Alo + aoff, 16);
            const int br = n0 + row;
            const u32 sz = (br < Nact) ? 16u : 0u;
            const int brc = (br < Nact) ? br : (Nact - 1);
            cpa16(dst + 2 * TILE_B, Bh + (size_t)brc * 256 + k0 + seg * 8, sz);
        }
        cp_commit();
    };

    const u32 arow = (wm + (lane & 15)) * 80 + (lane >> 4) * 16;
    const u32 brow = (wn + (lane & 7) + ((lane >> 4) & 1) * 8) * 80 + ((lane >> 3) & 1) * 16;

    load_chunk(0, 0);
    load_chunk(32, 1);

#pragma unroll 1
    for (int ic = 0; ic < 8; ic++) {
        if (ic < 7) asm volatile("cp.async.wait_group 1;" ::: "memory");
        else        asm volatile("cp.async.wait_group 0;" ::: "memory");
        __syncthreads();
        if (ic < 6) load_chunk((ic + 2) * 32, (ic + 2) % 3);

        const u32 base = sb + (ic % 3) * STAGE_B;
        const u32 aHi = base, aLo = base + TILE_B, bHm = base + 2 * TILE_B;
#pragma unroll
        for (int kk = 0; kk < 2; kk++) {
            u32 af[4][4], bf[2][4];
#pragma unroll
            for (int jb = 0; jb < 2; jb++)
                ldsm_x4(bf[jb], bHm + brow + jb * 16 * 80 + kk * 32);
#pragma unroll
            for (int im = 0; im < 4; im++)
                ldsm_x4(af[im], aHi + arow + im * 16 * 80 + kk * 32);
#pragma unroll
            for (int im = 0; im < 4; im++)
#pragma unroll
                for (int jn = 0; jn < 4; jn++)
                    mma_f16(acc[im][jn], af[im], &bf[jn >> 1][(jn & 1) * 2]);
#pragma unroll
            for (int im = 0; im < 4; im++)
                ldsm_x4(af[im], aLo + arow + im * 16 * 80 + kk * 32);
#pragma unroll
            for (int im = 0; im < 4; im++)
#pragma unroll
                for (int jn = 0; jn < 4; jn++)
                    mma_f16(acc[im][jn], af[im], &bf[jn >> 1][(jn & 1) * 2]);
        }
    }

    const int rbase = m0 + wm + (lane >> 2);
    const int cbase = n0 + wn + (lane & 3) * 2;
#pragma unroll
    for (int im = 0; im < 4; im++) {
#pragma unroll
        for (int jn = 0; jn < 4; jn++) {
            int n = cbase + jn * 8;
            if (n < Nact) {
                float bx = bias[n], by = bias[n + 1];
                int r0 = rbase + im * 16;
                *reinterpret_cast<float2*>(C + (size_t)r0 * Nact + n) =
                    make_float2(acc[im][jn][0] + bx, acc[im][jn][1] + by);
                *reinterpret_cast<float2*>(C + (size_t)(r0 + 8) * Nact + n) =
                    make_float2(acc[im][jn][2] + bx, acc[im][jn][3] + by);
            }
        }
    }
}

// ---------------- recurrence v6: no-spill 128/128 split, single CTA/batch ----------------
// 256 threads, thread r owns full output row r.
// k[0,128): smem weights, transposed [k4][r] float4 layout (conflict-free LDS.128).
// k[128,256): exactly 64 u64 registers (128 regs; total ~190 -> no spill).
// h double-buffered (1 barrier/step), pre[t+1] prefetched, 4 FFMA2 chains,
// fast tanh, fused fp16 hi/lo output for the next GEMM.
#define SW4 32
#define SCAN_SMEM (SW4 * 256 * 16 + 2 * 256 * 4)
__global__ void __launch_bounds__(256, 1) rnn_scan(
    const float* __restrict__ pre, const float* __restrict__ Whh,
    const float* __restrict__ bhh, __half* __restrict__ outhi, __half* __restrict__ outlo,
    float* __restrict__ hlast)
{
    extern __shared__ __align__(16) float sm[];
    float4* w4 = reinterpret_cast<float4*>(sm);          // [k4*256 + r]
    float* hbuf = sm + SW4 * 256 * 4;                    // 2 x 256
    const int b = blockIdx.x, r = threadIdx.x;

    // smem weights: k in [0,128)
#pragma unroll
    for (int k4 = 0; k4 < SW4; k4++)
        w4[k4 * 256 + r] = *reinterpret_cast<const float4*>(&Whh[r * 256 + k4 * 4]);

    // register weights: k in [128,256) -> 64 u64 (128 regs)
    u64 wreg[64];
#pragma unroll
    for (int j = 0; j < 32; j++) {
        ulonglong2 v = *reinterpret_cast<const ulonglong2*>(&Whh[r * 256 + 128 + j * 4]);
        wreg[2 * j] = v.x; wreg[2 * j + 1] = v.y;
    }
    const float bias = bhh[r];
    hbuf[r] = 0.f;
    __syncthreads();

    const float* preb = pre + (size_t)b * Tc * Hc;
    __half* ohi = outhi + (size_t)b * Tc * Hc;
    __half* olo = outlo + (size_t)b * Tc * Hc;
    const ulonglong2* w2s = reinterpret_cast<const ulonglong2*>(sm);

    float pc = preb[r];
    float hn = 0.f;
#pragma unroll 1
    for (int t = 0; t < Tc; t++) {
        int tn = (t + 1 < Tc) ? t + 1 : t;
        float pn = preb[tn * Hc + r];                    // prefetch next step
        const ulonglong2* hc = reinterpret_cast<const ulonglong2*>(hbuf + (t & 1) * 256);
        u64 a0 = pk2(pc + bias, 0.f), a1 = 0ull, a2 = 0ull, a3 = 0ull;
#pragma unroll
        for (int k4 = 0; k4 < SW4; k4++) {               // smem half
            ulonglong2 w = w2s[k4 * 256 + r];
            ulonglong2 h = hc[k4];
            a0 = fma2(w.x, h.x, a0);
            a1 = fma2(w.y, h.y, a1);
        }
#pragma unroll
        for (int j = 0; j < 32; j++) {                   // register half
            ulonglong2 h = hc[32 + j];
            a2 = fma2(wreg[2 * j], h.x, a2);
            a3 = fma2(wreg[2 * j + 1], h.y, a3);
        }
        float2 p0 = up2(a0), p1 = up2(a1), p2 = up2(a2), p3 = up2(a3);
        hn = tanh_acc(((p0.x + p0.y) + (p1.x + p1.y)) + ((p2.x + p2.y) + (p3.x + p3.y)));
        __half hh = __float2half_rn(hn);
        __half hl = __float2half_rn(hn - __half2float(hh));
        ohi[t * Hc + r] = hh;
        olo[t * Hc + r] = hl;
        hbuf[((t + 1) & 1) * 256 + r] = hn;
        __syncthreads();
        pc = pn;
    }
    hlast[b * Hc + r] = hn;
}

__global__ void tail_kernel(const int* __restrict__ x, float* __restrict__ outSeq) {
    int i = threadIdx.x;
    outSeq[i] = (float)x[i * T2c + (T2c - 1)];
}

extern "C" void kernel_launch(void* const* d_in, const int* in_sizes, int n_in,
                              void* d_out, int out_size) {
    const int*   x    = (const int*)d_in[0];
    const float* tab  = (const float*)d_in[1];
    const float* Wih  = (const float*)d_in[2];
    const float* Whh  = (const float*)d_in[3];
    const float* bih  = (const float*)d_in[4];
    const float* bhh  = (const float*)d_in[5];
    const float* Wout = (const float*)d_in[6];
    const float* bout = (const float*)d_in[7];
    float* out = (float*)d_out;

    float* pre;
    __half *ahi, *alo, *whi;
    cudaGetSymbolAddress((void**)&pre, g_pre);
    cudaGetSymbolAddress((void**)&ahi, g_ahi);
    cudaGetSymbolAddress((void**)&alo, g_alo);
    cudaGetSymbolAddress((void**)&whi, g_whi);

    cudaFuncSetAttribute(mma_gemm, cudaFuncAttributeMaxDynamicSharedMemorySize, GEMM_SMEM);
    cudaFuncSetAttribute(rnn_scan, cudaFuncAttributeMaxDynamicSharedMemorySize, SCAN_SMEM);

    const size_t LOGITS = (size_t)Bc * Tc * Vc;
    float* lstate = out + LOGITS;
    float* seq = out + LOGITS + 2 * Bc * Hc;

    embed_kernel<<<Bc * Tc, 64>>>(x, tab, ahi, alo);

    dim3 blk(256);
    // layer 0
    convw_kernel<<<(Hc * Ec) / 1024, 256>>>(Wih, whi);
    mma_gemm<<<dim3(2, 256), blk, GEMM_SMEM>>>(ahi, alo, whi, bih, pre, Hc);
    rnn_scan<<<Bc, 256, SCAN_SMEM>>>(pre, Whh, bhh, ahi, alo, lstate);
    // layer 1
    convw_kernel<<<(Hc * Ec) / 1024, 256>>>(Wih + Hc * Ec, whi);
    mma_gemm<<<dim3(2, 256), blk, GEMM_SMEM>>>(ahi, alo, whi, bih + Hc, pre, Hc);
    rnn_scan<<<Bc, 256, SCAN_SMEM>>>(pre, Whh + Hc * Hc, bhh + Hc, ahi, alo, lstate + Bc * Hc);
    // output projection
    convw_kernel<<<(Vc * Hc) / 1024, 256>>>(Wout, whi);
    mma_gemm<<<dim3((Vc + 127) / 128, 256), blk, GEMM_SMEM>>>(ahi, alo, whi, bout, out, Vc);

    tail_kernel<<<1, Bc>>>(x, seq);
}